// round 5
// baseline (speedup 1.0000x reference)
#include <cuda_runtime.h>

// Problem constants (fixed shapes per reference)
#define B_SZ 32768
#define D_SZ 256
#define K_SZ 1024

// GEMM tiling
#define BM 128
#define BN 128
#define BKD 16
#define TM 8
#define TN 8
#define NTHREADS 256   // (BM/TM)*(BN/TN) = 16*16

// Scratch: reciprocal squared-norms of codebook rows
__device__ float g_inv_norms[K_SZ];

// ---------------------------------------------------------------------------
// Kernel 1: inv_norms[k] = 1 / sum_d C[k,d]^2   (one warp per code)
// ---------------------------------------------------------------------------
__global__ void vq_norms_kernel(const float* __restrict__ C) {
    int k = blockIdx.x;
    int lane = threadIdx.x;  // 32 threads
    const float4* row = reinterpret_cast<const float4*>(C + (size_t)k * D_SZ);
    float s = 0.f;
#pragma unroll
    for (int i = 0; i < (D_SZ / 4) / 32; i++) {   // 2 iterations
        float4 v = row[lane + 32 * i];
        s += v.x * v.x + v.y * v.y + v.z * v.z + v.w * v.w;
    }
#pragma unroll
    for (int o = 16; o > 0; o >>= 1) s += __shfl_xor_sync(0xffffffffu, s, o);
    if (lane == 0) g_inv_norms[k] = 1.0f / s;
}

// ---------------------------------------------------------------------------
// Kernel 2: fused SGEMM (E @ C^T) + running argmax(dot^2 * inv_norm) + gather
// One block handles BM=128 embedding rows against all K=1024 codes.
// ---------------------------------------------------------------------------
__global__ __launch_bounds__(NTHREADS) void vq_main_kernel(
    const float* __restrict__ E,   // [B, D]
    const float* __restrict__ C,   // [K, D]
    float* __restrict__ z_out,     // [B, D]
    float* __restrict__ idx_out,   // [B] (as float)
    int write_idx)
{
    __shared__ float As[BKD][BM];   // 8 KB
    __shared__ float Bs[BKD][BN];   // 8 KB
    // cross-thread argmax reduction storage (per row, 16 candidates)
    __shared__ float s_score[BM][16];  // 8 KB
    __shared__ int   s_bidx[BM][16];   // 8 KB
    __shared__ float s_bdot[BM][16];   // 8 KB
    __shared__ float s_alpha[BM];
    __shared__ int   s_final[BM];

    const int tid = threadIdx.x;
    const int tx = tid & 15;       // code-tile column group
    const int ty = tid >> 4;       // row group
    const int row0 = blockIdx.x * BM;

    float best_score[TM];
    int   best_idx[TM];
    float best_dot[TM];
#pragma unroll
    for (int i = 0; i < TM; i++) { best_score[i] = -1.0f; best_idx[i] = 0; best_dot[i] = 0.0f; }

    for (int ct = 0; ct < K_SZ / BN; ct++) {          // 8 code tiles
        const int code0 = ct * BN;
        float acc[TM][TN];
#pragma unroll
        for (int i = 0; i < TM; i++)
#pragma unroll
            for (int j = 0; j < TN; j++) acc[i][j] = 0.0f;

        for (int kk = 0; kk < D_SZ; kk += BKD) {      // 16 k-chunks
            // Load A tile (128 rows x 16 cols) transposed into As[k][m]
#pragma unroll
            for (int i = 0; i < 2; i++) {
                int f = tid + NTHREADS * i;           // 0..511 float4 slots
                int r = f >> 2;                       // 0..127
                int c = (f & 3) * 4;                  // 0,4,8,12
                float4 v = *reinterpret_cast<const float4*>(
                    E + (size_t)(row0 + r) * D_SZ + kk + c);
                As[c + 0][r] = v.x; As[c + 1][r] = v.y;
                As[c + 2][r] = v.z; As[c + 3][r] = v.w;
            }
            // Load B tile (128 codes x 16 cols) transposed into Bs[k][n]
#pragma unroll
            for (int i = 0; i < 2; i++) {
                int f = tid + NTHREADS * i;
                int r = f >> 2;
                int c = (f & 3) * 4;
                float4 v = *reinterpret_cast<const float4*>(
                    C + (size_t)(code0 + r) * D_SZ + kk + c);
                Bs[c + 0][r] = v.x; Bs[c + 1][r] = v.y;
                Bs[c + 2][r] = v.z; Bs[c + 3][r] = v.w;
            }
            __syncthreads();

#pragma unroll
            for (int k = 0; k < BKD; k++) {
                float a[TM], b[TN];
#pragma unroll
                for (int i = 0; i < TM; i += 4)
                    *reinterpret_cast<float4*>(&a[i]) =
                        *reinterpret_cast<const float4*>(&As[k][ty * TM + i]);
#pragma unroll
                for (int j = 0; j < TN; j += 4)
                    *reinterpret_cast<float4*>(&b[j]) =
                        *reinterpret_cast<const float4*>(&Bs[k][tx * TN + j]);
#pragma unroll
                for (int i = 0; i < TM; i++)
#pragma unroll
                    for (int j = 0; j < TN; j++)
                        acc[i][j] = fmaf(a[i], b[j], acc[i][j]);
            }
            __syncthreads();
        }

        // Epilogue for this code tile: fold into per-row running argmax.
        // score = dot^2 * inv_norm; argmax(score) == argmin(error).
#pragma unroll
        for (int j = 0; j < TN; j++) {
            int code = code0 + tx * TN + j;
            float invn = __ldg(&g_inv_norms[code]);
#pragma unroll
            for (int i = 0; i < TM; i++) {
                float d = acc[i][j];
                float s = d * d * invn;
                if (s > best_score[i]) {   // strict > keeps earliest index
                    best_score[i] = s;
                    best_idx[i] = code;
                    best_dot[i] = d;
                }
            }
        }
    }

    // Cross-thread reduction: 16 candidates per row (one per tx).
#pragma unroll
    for (int i = 0; i < TM; i++) {
        int r = ty * TM + i;
        s_score[r][tx] = best_score[i];
        s_bidx[r][tx]  = best_idx[i];
        s_bdot[r][tx]  = best_dot[i];
    }
    __syncthreads();

    if (tid < BM) {
        float bs = -1.0f; int bi = 0; float bd = 0.0f;
#pragma unroll
        for (int t = 0; t < 16; t++) {
            float sc = s_score[tid][t];
            int   ix = s_bidx[tid][t];
            if (sc > bs || (sc == bs && ix < bi)) {
                bs = sc; bi = ix; bd = s_bdot[tid][t];
            }
        }
        float alpha = bd * __ldg(&g_inv_norms[bi]);
        s_alpha[tid] = alpha;
        s_final[tid] = bi;
        if (write_idx) idx_out[row0 + tid] = (float)bi;
    }
    __syncthreads();

    // Write z = alpha * C[idx]: 256 threads, 4 rows per pass (64 float4/row).
#pragma unroll 4
    for (int p = 0; p < BM / 4; p++) {
        int r  = p * 4 + (tid >> 6);
        int d4 = tid & 63;
        float a = s_alpha[r];
        int   ci = s_final[r];
        float4 cv = __ldg(reinterpret_cast<const float4*>(C + (size_t)ci * D_SZ) + d4);
        float4 o = make_float4(a * cv.x, a * cv.y, a * cv.z, a * cv.w);
        *(reinterpret_cast<float4*>(z_out + (size_t)(row0 + r) * D_SZ) + d4) = o;
    }
}

// ---------------------------------------------------------------------------
extern "C" void kernel_launch(void* const* d_in, const int* in_sizes, int n_in,
                              void* d_out, int out_size) {
    const float* E = (const float*)d_in[0];   // embedding [B, D]
    const float* C = (const float*)d_in[1];   // codebook  [K, D]
    float* z = (float*)d_out;                 // z_out [B*D], then indices [B]
    float* idx = z + (size_t)B_SZ * D_SZ;
    int write_idx = (out_size >= B_SZ * D_SZ + B_SZ) ? 1 : 0;

    vq_norms_kernel<<<K_SZ, 32>>>(C);
    vq_main_kernel<<<B_SZ / BM, NTHREADS>>>(E, C, z, idx, write_idx);
}

// round 6
// speedup vs baseline: 1.0593x; 1.0593x over previous
#include <cuda_runtime.h>

// Problem constants (fixed shapes per reference)
#define B_SZ 32768
#define D_SZ 256
#define K_SZ 1024

// GEMM tiling
#define BM 128
#define BN 128
#define BKD 16
#define TM 8
#define TN 8
#define NTHREADS 256   // (BM/TM)*(BN/TN) = 16*16

// Scratch: reciprocal squared-norms of codebook rows
__device__ float g_inv_norms[K_SZ];

// ---------------------------------------------------------------------------
// Kernel 1: inv_norms[k] = 1 / sum_d C[k,d]^2   (one warp per code)
// ---------------------------------------------------------------------------
__global__ void vq_norms_kernel(const float* __restrict__ C) {
    int k = blockIdx.x;
    int lane = threadIdx.x;  // 32 threads
    const float4* row = reinterpret_cast<const float4*>(C + (size_t)k * D_SZ);
    float s = 0.f;
#pragma unroll
    for (int i = 0; i < (D_SZ / 4) / 32; i++) {   // 2 iterations
        float4 v = row[lane + 32 * i];
        s += v.x * v.x + v.y * v.y + v.z * v.z + v.w * v.w;
    }
#pragma unroll
    for (int o = 16; o > 0; o >>= 1) s += __shfl_xor_sync(0xffffffffu, s, o);
    if (lane == 0) g_inv_norms[k] = 1.0f / s;
}

// ---------------------------------------------------------------------------
// Kernel 2: fused SGEMM (E @ C^T) + running argmax(dot^2 * inv_norm) + gather
// One block handles BM=128 embedding rows against all K=1024 codes.
// ---------------------------------------------------------------------------
__global__ __launch_bounds__(NTHREADS) void vq_main_kernel(
    const float* __restrict__ E,   // [B, D]
    const float* __restrict__ C,   // [K, D]
    float* __restrict__ z_out,     // [B, D]
    float* __restrict__ idx_out,   // [B] (as float)
    int write_idx)
{
    __shared__ float As[BKD][BM];   // 8 KB
    __shared__ float Bs[BKD][BN];   // 8 KB
    // cross-thread argmax reduction storage (per row, 16 candidates)
    __shared__ float s_score[BM][16];  // 8 KB
    __shared__ int   s_bidx[BM][16];   // 8 KB
    __shared__ float s_bdot[BM][16];   // 8 KB
    __shared__ float s_alpha[BM];
    __shared__ int   s_final[BM];

    const int tid = threadIdx.x;
    const int tx = tid & 15;       // code-tile column group
    const int ty = tid >> 4;       // row group
    const int row0 = blockIdx.x * BM;

    float best_score[TM];
    int   best_idx[TM];
    float best_dot[TM];
#pragma unroll
    for (int i = 0; i < TM; i++) { best_score[i] = -1.0f; best_idx[i] = 0; best_dot[i] = 0.0f; }

    for (int ct = 0; ct < K_SZ / BN; ct++) {          // 8 code tiles
        const int code0 = ct * BN;
        float acc[TM][TN];
#pragma unroll
        for (int i = 0; i < TM; i++)
#pragma unroll
            for (int j = 0; j < TN; j++) acc[i][j] = 0.0f;

        for (int kk = 0; kk < D_SZ; kk += BKD) {      // 16 k-chunks
            // Load A tile (128 rows x 16 cols) transposed into As[k][m]
#pragma unroll
            for (int i = 0; i < 2; i++) {
                int f = tid + NTHREADS * i;           // 0..511 float4 slots
                int r = f >> 2;                       // 0..127
                int c = (f & 3) * 4;                  // 0,4,8,12
                float4 v = *reinterpret_cast<const float4*>(
                    E + (size_t)(row0 + r) * D_SZ + kk + c);
                As[c + 0][r] = v.x; As[c + 1][r] = v.y;
                As[c + 2][r] = v.z; As[c + 3][r] = v.w;
            }
            // Load B tile (128 codes x 16 cols) transposed into Bs[k][n]
#pragma unroll
            for (int i = 0; i < 2; i++) {
                int f = tid + NTHREADS * i;
                int r = f >> 2;
                int c = (f & 3) * 4;
                float4 v = *reinterpret_cast<const float4*>(
                    C + (size_t)(code0 + r) * D_SZ + kk + c);
                Bs[c + 0][r] = v.x; Bs[c + 1][r] = v.y;
                Bs[c + 2][r] = v.z; Bs[c + 3][r] = v.w;
            }
            __syncthreads();

#pragma unroll
            for (int k = 0; k < BKD; k++) {
                float a[TM], b[TN];
#pragma unroll
                for (int i = 0; i < TM; i += 4)
                    *reinterpret_cast<float4*>(&a[i]) =
                        *reinterpret_cast<const float4*>(&As[k][ty * TM + i]);
#pragma unroll
                for (int j = 0; j < TN; j += 4)
                    *reinterpret_cast<float4*>(&b[j]) =
                        *reinterpret_cast<const float4*>(&Bs[k][tx * TN + j]);
#pragma unroll
                for (int i = 0; i < TM; i++)
#pragma unroll
                    for (int j = 0; j < TN; j++)
                        acc[i][j] = fmaf(a[i], b[j], acc[i][j]);
            }
            __syncthreads();
        }

        // Epilogue for this code tile: fold into per-row running argmax.
        // score = dot^2 * inv_norm; argmax(score) == argmin(error).
#pragma unroll
        for (int j = 0; j < TN; j++) {
            int code = code0 + tx * TN + j;
            float invn = __ldg(&g_inv_norms[code]);
#pragma unroll
            for (int i = 0; i < TM; i++) {
                float d = acc[i][j];
                float s = d * d * invn;
                if (s > best_score[i]) {   // strict > keeps earliest index
                    best_score[i] = s;
                    best_idx[i] = code;
                    best_dot[i] = d;
                }
            }
        }
    }

    // Cross-thread reduction: 16 candidates per row (one per tx).
#pragma unroll
    for (int i = 0; i < TM; i++) {
        int r = ty * TM + i;
        s_score[r][tx] = best_score[i];
        s_bidx[r][tx]  = best_idx[i];
        s_bdot[r][tx]  = best_dot[i];
    }
    __syncthreads();

    if (tid < BM) {
        float bs = -1.0f; int bi = 0; float bd = 0.0f;
#pragma unroll
        for (int t = 0; t < 16; t++) {
            float sc = s_score[tid][t];
            int   ix = s_bidx[tid][t];
            if (sc > bs || (sc == bs && ix < bi)) {
                bs = sc; bi = ix; bd = s_bdot[tid][t];
            }
        }
        float alpha = bd * __ldg(&g_inv_norms[bi]);
        s_alpha[tid] = alpha;
        s_final[tid] = bi;
        if (write_idx) idx_out[row0 + tid] = (float)bi;
    }
    __syncthreads();

    // Write z = alpha * C[idx]: 256 threads, 4 rows per pass (64 float4/row).
#pragma unroll 4
    for (int p = 0; p < BM / 4; p++) {
        int r  = p * 4 + (tid >> 6);
        int d4 = tid & 63;
        float a = s_alpha[r];
        int   ci = s_final[r];
        float4 cv = __ldg(reinterpret_cast<const float4*>(C + (size_t)ci * D_SZ) + d4);
        float4 o = make_float4(a * cv.x, a * cv.y, a * cv.z, a * cv.w);
        *(reinterpret_cast<float4*>(z_out + (size_t)(row0 + r) * D_SZ) + d4) = o;
    }
}

// ---------------------------------------------------------------------------
extern "C" void kernel_launch(void* const* d_in, const int* in_sizes, int n_in,
                              void* d_out, int out_size) {
    const float* E = (const float*)d_in[0];   // embedding [B, D]
    const float* C = (const float*)d_in[1];   // codebook  [K, D]
    float* z = (float*)d_out;                 // z_out [B*D], then indices [B]
    float* idx = z + (size_t)B_SZ * D_SZ;
    int write_idx = (out_size >= B_SZ * D_SZ + B_SZ) ? 1 : 0;

    vq_norms_kernel<<<K_SZ, 32>>>(C);
    vq_main_kernel<<<B_SZ / BM, NTHREADS>>>(E, C, z, idx, write_idx);
}

// round 10
// speedup vs baseline: 1.3537x; 1.2779x over previous
#include <cuda_runtime.h>
#include <cuda_bf16.h>
#include <cstdint>

// ===========================================================================
// Problem constants
// ===========================================================================
#define B_SZ 32768
#define D_SZ 256
#define K_SZ 1024

// K3 GEMM tiling: CTA = 128 rows x 256 codes (one quarter), 2 passes of 128
#define NTHREADS 256
#define BK 32              // d-chunk per pipeline stage

// SMEM layout (bytes). Tiles: [buf][tile] tile= Ahi,Alo,Bhi,Blo; each 128x40 bf16
#define T_STRIDE 80        // bytes per smem row (32 bf16 + 8 pad = 40 elems)
#define TILE_SZ  10240     // 128 * 80
#define BUF_SZ   40960     // 4 tiles
#define OFF_INVN 81920     // 256 floats for this quarter's codes
#define OFF_CS1  82944     // float [128][8]
#define OFF_CI1  87040     // int   [128][8]
#define OFF_CS2  91136     // float [128][8]
#define SMEM_K3  95232

// ===========================================================================
// Device scratch (allocation-free rule: __device__ globals)
// ===========================================================================
__device__ float g_inv_norms[K_SZ];
__device__ __align__(16) __nv_bfloat16 g_Ehi[B_SZ * D_SZ];
__device__ __align__(16) __nv_bfloat16 g_Elo[B_SZ * D_SZ];
__device__ __align__(16) __nv_bfloat16 g_Chi[K_SZ * D_SZ];
__device__ __align__(16) __nv_bfloat16 g_Clo[K_SZ * D_SZ];
// per (quarter, row) top-2 approx results
__device__ float g_ts1[4 * B_SZ];
__device__ int   g_ti1[4 * B_SZ];
__device__ float g_ts2[4 * B_SZ];

// ===========================================================================
// PTX helpers (plain sm_103-safe: mma.sync / ldmatrix / cp.async only)
// ===========================================================================
__device__ __forceinline__ uint32_t smem_u32(const void* p) {
    uint32_t a;
    asm("{ .reg .u64 t; cvta.to.shared.u64 t, %1; cvt.u32.u64 %0, t; }" : "=r"(a) : "l"(p));
    return a;
}
__device__ __forceinline__ void ldsm_x4(uint32_t r[4], uint32_t addr) {
    asm volatile("ldmatrix.sync.aligned.m8n8.x4.shared.b16 {%0,%1,%2,%3}, [%4];"
                 : "=r"(r[0]), "=r"(r[1]), "=r"(r[2]), "=r"(r[3]) : "r"(addr));
}
__device__ __forceinline__ void mma_bf16(float d[4], const uint32_t a[4], const uint32_t* b) {
    asm volatile(
        "mma.sync.aligned.m16n8k16.row.col.f32.bf16.bf16.f32 "
        "{%0,%1,%2,%3}, {%4,%5,%6,%7}, {%8,%9}, {%0,%1,%2,%3};"
        : "+f"(d[0]), "+f"(d[1]), "+f"(d[2]), "+f"(d[3])
        : "r"(a[0]), "r"(a[1]), "r"(a[2]), "r"(a[3]), "r"(b[0]), "r"(b[1]));
}
#define CP_ASYNC16(dst, src) \
    asm volatile("cp.async.cg.shared.global [%0], [%1], 16;" :: "r"(dst), "l"(src) : "memory")
#define CP_COMMIT() asm volatile("cp.async.commit_group;" ::: "memory")
#define CP_WAIT(N)  asm volatile("cp.async.wait_group %0;" :: "n"(N) : "memory")

__device__ __forceinline__ float warp_allsum(float v) {
#pragma unroll
    for (int o = 16; o > 0; o >>= 1) v += __shfl_xor_sync(0xffffffffu, v, o);
    return v;
}

// ===========================================================================
// K1: inv_norms[k] = 1 / ||C[k]||^2   (one warp per code)
// ===========================================================================
__global__ void vq_norms_kernel(const float* __restrict__ C) {
    int k = blockIdx.x;
    int lane = threadIdx.x;
    const float4* row = reinterpret_cast<const float4*>(C + (size_t)k * D_SZ);
    float s = 0.f;
#pragma unroll
    for (int i = 0; i < 2; i++) {
        float4 v = row[lane + 32 * i];
        s += v.x * v.x + v.y * v.y + v.z * v.z + v.w * v.w;
    }
    s = warp_allsum(s);
    if (lane == 0) g_inv_norms[k] = 1.0f / s;
}

// ===========================================================================
// K2: 2-limb bf16 split (a ~= hi + lo, ~17 mantissa bits)
// ===========================================================================
__global__ void vq_split_kernel(const float* __restrict__ src, int n8, int isC) {
    int i = blockIdx.x * blockDim.x + threadIdx.x;
    if (i >= n8) return;
    __nv_bfloat16* dh = isC ? g_Chi : g_Ehi;
    __nv_bfloat16* dl = isC ? g_Clo : g_Elo;
    const float4* p = reinterpret_cast<const float4*>(src) + (size_t)i * 2;
    float4 f0 = p[0], f1 = p[1];
    float v[8] = {f0.x, f0.y, f0.z, f0.w, f1.x, f1.y, f1.z, f1.w};
    union U8 { __nv_bfloat16 h[8]; uint4 u; } uh, ul;
#pragma unroll
    for (int j = 0; j < 8; j++) {
        float a = v[j];
        __nv_bfloat16 bh = __float2bfloat16_rn(a);
        float r = a - __bfloat162float(bh);
        uh.h[j] = bh;
        ul.h[j] = __float2bfloat16_rn(r);
    }
    *reinterpret_cast<uint4*>(dh + (size_t)i * 8) = uh.u;
    *reinterpret_cast<uint4*>(dl + (size_t)i * 8) = ul.u;
}

// ===========================================================================
// K3: 3-term split-bf16 mma.sync GEMM + per-row approx top-2
// grid = 1024: blockIdx = rb*4 + q  (rb: 128-row block, q: 256-code quarter)
// ===========================================================================
__global__ __launch_bounds__(NTHREADS, 1) void vq_gemm_kernel() {
    extern __shared__ char smem[];
    const uint32_t sb = smem_u32(smem);
    const int tid = threadIdx.x;
    const int lane = tid & 31;
    const int wid = tid >> 5;
    const int wm = wid & 3;        // M group: rows wm*32..+32
    const int wn = wid >> 2;       // N half:  codes wn*64..+64 (within 128-pass)
    const int rb = blockIdx.x >> 2;
    const int q  = blockIdx.x & 3;
    const int rowA0 = rb * 128;

    float* s_invn = reinterpret_cast<float*>(smem + OFF_INVN);
    float* c_s1 = reinterpret_cast<float*>(smem + OFF_CS1);
    int*   c_i1 = reinterpret_cast<int*>(smem + OFF_CI1);
    float* c_s2 = reinterpret_cast<float*>(smem + OFF_CS2);

    s_invn[tid] = g_inv_norms[q * 256 + tid];
    __syncthreads();

    // per-thread top-2 state for 4 owned rows (mt*2 + half)
    float st_s1[4], st_s2[4];
    int   st_i1[4];
#pragma unroll
    for (int i = 0; i < 4; i++) { st_s1[i] = -1.f; st_s2[i] = -1.f; st_i1[i] = 0; }

    // chunk loader: 8 x 16B cp.async per thread into buffer `buf`
    auto loadChunk = [&](int buf, int kk, int codeB0) {
#pragma unroll
        for (int j = 0; j < 8; j++) {
            int id = tid + NTHREADS * j;          // 0..2047
            int tl = id >> 9;                     // 0 Ahi,1 Alo,2 Bhi,3 Blo
            int w  = id & 511;
            int r  = w >> 2;                      // 0..127
            int c  = w & 3;                       // 16B column
            const __nv_bfloat16* base =
                (tl == 0) ? g_Ehi : (tl == 1) ? g_Elo : (tl == 2) ? g_Chi : g_Clo;
            int grow = (tl < 2) ? (rowA0 + r) : (codeB0 + r);
            const void* src = base + (size_t)grow * D_SZ + kk + c * 8;
            uint32_t dst = sb + buf * BUF_SZ + tl * TILE_SZ + r * T_STRIDE + c * 16;
            CP_ASYNC16(dst, src);
        }
        CP_COMMIT();
    };

    for (int p = 0; p < 2; p++) {
        const int codeB0 = q * 256 + p * 128;
        float d[2][8][4];
#pragma unroll
        for (int mt = 0; mt < 2; mt++)
#pragma unroll
            for (int nt = 0; nt < 8; nt++)
#pragma unroll
                for (int e = 0; e < 4; e++) d[mt][nt][e] = 0.f;

        loadChunk(0, 0, codeB0);
        for (int kc = 0; kc < 8; kc++) {
            const int buf = kc & 1;
            if (kc < 7) { loadChunk(buf ^ 1, (kc + 1) * BK, codeB0); CP_WAIT(1); }
            else        { CP_WAIT(0); }
            __syncthreads();

#pragma unroll
            for (int ks2 = 0; ks2 < 2; ks2++) {
                const int ks = ks2 * 16;
                // A fragments: [limb][mt][4]
                uint32_t afr[2][2][4];
                {
                    int mi = lane >> 3;
                    int arow_off = ((mi & 1) * 8 + (lane & 7)) * T_STRIDE;
                    int akoff = (ks + (mi >> 1) * 8) * 2;
#pragma unroll
                    for (int lb = 0; lb < 2; lb++)
#pragma unroll
                        for (int mt = 0; mt < 2; mt++) {
                            uint32_t ad = sb + buf * BUF_SZ + lb * TILE_SZ
                                        + (wm * 32 + mt * 16) * T_STRIDE + arow_off + akoff;
                            ldsm_x4(afr[lb][mt], ad);
                        }
                }
                // B fragments per n-tile pair, then MMAs
#pragma unroll
                for (int np = 0; np < 4; np++) {
                    uint32_t bh[4], bl[4];
                    int mi = lane >> 3;
                    int brow_off = ((mi >> 1) * 8 + (lane & 7)) * T_STRIDE;
                    int bkoff = (ks + (mi & 1) * 8) * 2;
                    uint32_t bd0 = sb + buf * BUF_SZ + 2 * TILE_SZ
                                 + (wn * 64 + np * 16) * T_STRIDE + brow_off + bkoff;
                    uint32_t bd1 = bd0 + TILE_SZ;  // lo limb tile
                    ldsm_x4(bh, bd0);
                    ldsm_x4(bl, bd1);
#pragma unroll
                    for (int jj = 0; jj < 2; jj++) {
                        int nt = np * 2 + jj;
#pragma unroll
                        for (int mt = 0; mt < 2; mt++) {
                            mma_bf16(d[mt][nt], afr[0][mt], bh + jj * 2);  // hi*hi
                            mma_bf16(d[mt][nt], afr[0][mt], bl + jj * 2);  // hi*lo
                            mma_bf16(d[mt][nt], afr[1][mt], bh + jj * 2);  // lo*hi
                        }
                    }
                }
            }
            __syncthreads();
        }

        // epilogue: fold this pass's 128 codes into per-row top-2
#pragma unroll
        for (int mt = 0; mt < 2; mt++)
#pragma unroll
            for (int nt = 0; nt < 8; nt++) {
                int cb = wn * 64 + nt * 8 + (lane & 3) * 2;   // 0..127
                int cl = p * 128 + cb;
                float in0 = s_invn[cl], in1 = s_invn[cl + 1];
                int gc = q * 256 + cl;
#pragma unroll
                for (int half = 0; half < 2; half++) {
                    int si = mt * 2 + half;
                    float e0 = d[mt][nt][half * 2 + 0];
                    float e1 = d[mt][nt][half * 2 + 1];
                    float sc0 = e0 * e0 * in0;
                    if (sc0 > st_s1[si]) { st_s2[si] = st_s1[si]; st_s1[si] = sc0; st_i1[si] = gc; }
                    else if (sc0 > st_s2[si]) st_s2[si] = sc0;
                    float sc1 = e1 * e1 * in1;
                    if (sc1 > st_s1[si]) { st_s2[si] = st_s1[si]; st_s1[si] = sc1; st_i1[si] = gc + 1; }
                    else if (sc1 > st_s2[si]) st_s2[si] = sc1;
                }
            }
    }

    // cross-thread merge: 8 candidates per row
#pragma unroll
    for (int mt = 0; mt < 2; mt++)
#pragma unroll
        for (int half = 0; half < 2; half++) {
            int r = wm * 32 + mt * 16 + half * 8 + (lane >> 2);
            int slot = wn * 4 + (lane & 3);
            int si = mt * 2 + half;
            c_s1[r * 8 + slot] = st_s1[si];
            c_i1[r * 8 + slot] = st_i1[si];
            c_s2[r * 8 + slot] = st_s2[si];
        }
    __syncthreads();
    if (tid < 128) {
        float S1 = -1.f, S2 = -1.f; int I1 = 0;
#pragma unroll
        for (int s = 0; s < 8; s++) {
            float a1 = c_s1[tid * 8 + s];
            int   ai = c_i1[tid * 8 + s];
            float a2 = c_s2[tid * 8 + s];
            if (a1 > S1) { S2 = (S1 > a2) ? S1 : a2; I1 = ai; S1 = a1; }
            else if (a1 > S2) S2 = a1;
        }
        int o = q * B_SZ + rowA0 + tid;
        g_ts1[o] = S1; g_ti1[o] = I1; g_ts2[o] = S2;
    }
}

// ===========================================================================
// K4: finalize — certify winner or exact fp32 rescan; exact alpha; write z,idx
// one warp per row
// ===========================================================================
__global__ __launch_bounds__(256) void vq_final_kernel(
    const float* __restrict__ E, const float* __restrict__ C,
    float* __restrict__ z_out, float* __restrict__ idx_out, int write_idx)
{
    int row = blockIdx.x * 8 + (threadIdx.x >> 5);
    int lane = threadIdx.x & 31;
    const float4* E4 = reinterpret_cast<const float4*>(E);
    const float4* C4 = reinterpret_cast<const float4*>(C);

    float4 ev0 = E4[(size_t)row * 64 + lane * 2];
    float4 ev1 = E4[(size_t)row * 64 + lane * 2 + 1];
    float en2 = warp_allsum(ev0.x * ev0.x + ev0.y * ev0.y + ev0.z * ev0.z + ev0.w * ev0.w +
                            ev1.x * ev1.x + ev1.y * ev1.y + ev1.z * ev1.z + ev1.w * ev1.w);

    // merge 4 quarter top-2 triples
    float S1 = -1.f, S2 = -1.f; int I1 = 0;
#pragma unroll
    for (int qq = 0; qq < 4; qq++) {
        float a1 = g_ts1[qq * B_SZ + row];
        int   ai = g_ti1[qq * B_SZ + row];
        float a2 = g_ts2[qq * B_SZ + row];
        if (a1 > S1) { S2 = (S1 > a2) ? S1 : a2; I1 = ai; S1 = a1; }
        else if (a1 > S2) S2 = a1;
    }

    float eps = en2 * (1.0f / 8192.0f);   // 2^-13 * ||e||^2 (4x margin on bound)
    int kbest = I1;
    if (!(S1 - S2 > eps)) {
        // exact fp32 rescan of all codes (rare)
        float best = -1.f; kbest = 0;
        for (int k = 0; k < K_SZ; k++) {
            float4 c0 = C4[(size_t)k * 64 + lane * 2];
            float4 c1 = C4[(size_t)k * 64 + lane * 2 + 1];
            float pp = ev0.x * c0.x + ev0.y * c0.y + ev0.z * c0.z + ev0.w * c0.w +
                       ev1.x * c1.x + ev1.y * c1.y + ev1.z * c1.z + ev1.w * c1.w;
            float dot = warp_allsum(pp);
            float sc = dot * dot * g_inv_norms[k];
            if (sc > best) { best = sc; kbest = k; }   // strict > : first occurrence
        }
    }

    // exact dot for winner -> alpha, z
    float4 cv0 = C4[(size_t)kbest * 64 + lane * 2];
    float4 cv1 = C4[(size_t)kbest * 64 + lane * 2 + 1];
    float pp = ev0.x * cv0.x + ev0.y * cv0.y + ev0.z * cv0.z + ev0.w * cv0.w +
               ev1.x * cv1.x + ev1.y * cv1.y + ev1.z * cv1.z + ev1.w * cv1.w;
    float dot = warp_allsum(pp);
    float alpha = dot * g_inv_norms[kbest];
    float4* Z4 = reinterpret_cast<float4*>(z_out);
    Z4[(size_t)row * 64 + lane * 2] =
        make_float4(alpha * cv0.x, alpha * cv0.y, alpha * cv0.z, alpha * cv0.w);
    Z4[(size_t)row * 64 + lane * 2 + 1] =
        make_float4(alpha * cv1.x, alpha * cv1.y, alpha * cv1.z, alpha * cv1.w);
    if (lane == 0 && write_idx) idx_out[row] = (float)kbest;
}

// ===========================================================================
extern "C" void kernel_launch(void* const* d_in, const int* in_sizes, int n_in,
                              void* d_out, int out_size) {
    const float* E = (const float*)d_in[0];
    const float* C = (const float*)d_in[1];
    float* z = (float*)d_out;
    float* idx = z + (size_t)B_SZ * D_SZ;
    int write_idx = (out_size >= B_SZ * D_SZ + B_SZ) ? 1 : 0;

    cudaFuncSetAttribute(vq_gemm_kernel,
                         cudaFuncAttributeMaxDynamicSharedMemorySize, SMEM_K3);

    vq_norms_kernel<<<K_SZ, 32>>>(C);
    vq_split_kernel<<<(B_SZ * D_SZ / 8 + 255) / 256, 256>>>(E, B_SZ * D_SZ / 8, 0);
    vq_split_kernel<<<(K_SZ * D_SZ / 8 + 255) / 256, 256>>>(C, K_SZ * D_SZ / 8, 1);
    vq_gemm_kernel<<<1024, NTHREADS, SMEM_K3>>>();
    vq_final_kernel<<<B_SZ / 8, 256>>>(E, C, z, idx, write_idx);
}